// round 11
// baseline (speedup 1.0000x reference)
#include <cuda_runtime.h>
#include <cuda_bf16.h>
#include <cstdint>
#include <cstddef>

#define D_IN   4096
#define D_OUT  4096
#define MROWS  8192
#define RANK   32
#define KE     4160           // 4096 + 32 lora + 32 zero pad = 65*64
#define NCHUNK 65
#define STAGE_BYTES 65536     // Ahi 16K | Alo 16K | Bhi 16K | Blo 16K
#define SMEM_DYN (2 * STAGE_BYTES + 1024)

__device__ __nv_bfloat16 g_Ahi[(size_t)MROWS * KE];
__device__ __nv_bfloat16 g_Alo[(size_t)MROWS * KE];
__device__ __nv_bfloat16 g_Whi[(size_t)D_OUT * KE];
__device__ __nv_bfloat16 g_Wlo[(size_t)D_OUT * KE];
__device__ __nv_bfloat16 g_Xr [(size_t)MROWS * D_IN];
__device__ __nv_bfloat16 g_la [(size_t)RANK  * D_IN];

// ---------------------------------------------------------------- helpers
__device__ __forceinline__ uint32_t smem_u32(const void* p) {
    uint32_t a;
    asm("{ .reg .u64 t; cvta.to.shared.u64 t, %1; cvt.u32.u64 %0, t; }" : "=r"(a) : "l"(p));
    return a;
}
__device__ __forceinline__ void cp_async16(uint32_t dst, const void* src) {
    asm volatile("cp.async.cg.shared.global [%0], [%1], 16;" :: "r"(dst), "l"(src));
}
#define CP_COMMIT() asm volatile("cp.async.commit_group;" ::: "memory")
#define CP_WAIT_1() asm volatile("cp.async.wait_group 1;" ::: "memory")
#define CP_WAIT_0() asm volatile("cp.async.wait_group 0;" ::: "memory")

__device__ __forceinline__ void ldm_x4(uint32_t* r, uint32_t addr) {
    asm volatile("ldmatrix.sync.aligned.m8n8.x4.shared.b16 {%0,%1,%2,%3}, [%4];"
        : "=r"(r[0]), "=r"(r[1]), "=r"(r[2]), "=r"(r[3]) : "r"(addr));
}
__device__ __forceinline__ void mma16816(float* c, const uint32_t* a, const uint32_t* b) {
    asm volatile("mma.sync.aligned.m16n8k16.row.col.f32.bf16.bf16.f32 "
        "{%0,%1,%2,%3}, {%4,%5,%6,%7}, {%8,%9}, {%0,%1,%2,%3};"
        : "+f"(c[0]), "+f"(c[1]), "+f"(c[2]), "+f"(c[3])
        : "r"(a[0]), "r"(a[1]), "r"(a[2]), "r"(a[3]), "r"(b[0]), "r"(b[1]));
}
__device__ __forceinline__ void split_bf16(float v, __nv_bfloat16& h, __nv_bfloat16& l) {
    h = __float2bfloat16(v);
    l = __float2bfloat16(v - __bfloat162float(h));
}
// swizzled byte offset within a 128B-row tile: (row, 16B-unit)
__device__ __forceinline__ uint32_t swz(int r, int u) {
    return (uint32_t)(r * 128 + ((u ^ (r & 7)) * 16));
}

// ------------------------------------------------- K0: W split (+lora_b fold) + la->bf16
__global__ void __launch_bounds__(256) prep_w_kernel(const float* __restrict__ w,
                                                     const float* __restrict__ lb,
                                                     const float* __restrict__ la) {
    const size_t b = blockIdx.x;
    if (b < D_OUT) {
        for (int c = threadIdx.x; c < KE; c += 256) {
            float v = 0.0f;
            if (c < D_IN) v = w[b * D_IN + c];
            else if (c < D_IN + RANK) v = lb[b * RANK + (c - D_IN)];
            __nv_bfloat16 h, l;
            split_bf16(v, h, l);
            g_Whi[b * KE + c] = h;
            g_Wlo[b * KE + c] = l;
        }
    } else {
        const size_t r = b - D_OUT;   // 0..31
        for (int c = threadIdx.x; c < D_IN; c += 256)
            g_la[r * D_IN + c] = __float2bfloat16(la[r * D_IN + c]);
    }
}

// ------------------------------------------------- K1: rotate + NVFP4 quant + split
__device__ __forceinline__ float quantize_one(float v, float scale) {
    float an = fabsf(v) / scale;
    float lvl;
    if      (an <= 0.25f) lvl = 0.0f;   // ties -> lower level (argmin-first)
    else if (an <= 0.75f) lvl = 0.5f;
    else if (an <= 1.25f) lvl = 1.0f;
    else if (an <= 1.75f) lvl = 1.5f;
    else if (an <= 2.5f)  lvl = 2.0f;
    else if (an <= 3.5f)  lvl = 3.0f;
    else if (an <= 5.0f)  lvl = 4.0f;
    else                  lvl = 6.0f;
    return copysignf(lvl * scale, v);
}

__global__ void __launch_bounds__(256) rotate_quant_kernel(const float* __restrict__ x,
                                                           const float* __restrict__ S_in) {
    __shared__ float row_sm[D_IN];
    const int tid = threadIdx.x;
    const size_t row = blockIdx.x;

    const float* xr = x + row * D_IN;
    for (int i = tid; i < D_IN; i += 256) row_sm[i] = xr[i] * S_in[i];

    // FWHT per 128-block (Sylvester order == reference H_block, unnormalized)
    for (int st = 0; st < 7; st++) {
        __syncthreads();
        const int h = 1 << st;
        for (int p = tid; p < 2048; p += 256) {
            int seg = p >> 6, pi = p & 63;
            int base = (seg << 7) + ((pi >> st) << (st + 1)) + (pi & (h - 1));
            float a = row_sm[base], b = row_sm[base + h];
            row_sm[base] = a + b;
            row_sm[base + h] = a - b;
        }
    }
    __syncthreads();

    const float HN = 0.08838834764831845f;  // fl32(1/sqrt(128))
    const int b0 = tid << 4;
    float v[16], amax = 0.0f;
#pragma unroll
    for (int i = 0; i < 16; i++) {
        v[i] = row_sm[b0 + i] * HN;
        amax = fmaxf(amax, fabsf(v[i]));
    }
    amax = fmaxf(amax, 1e-12f);
    const float scale = amax / 6.0f;

    uint32_t hp[8], lp[8], xp[8];
#pragma unroll
    for (int i = 0; i < 16; i += 2) {
        float q0 = quantize_one(v[i], scale), q1 = quantize_one(v[i + 1], scale);
        __nv_bfloat16 h0, l0, h1, l1;
        split_bf16(q0, h0, l0);
        split_bf16(q1, h1, l1);
        hp[i >> 1] = (uint32_t)__bfloat16_as_ushort(h0) | ((uint32_t)__bfloat16_as_ushort(h1) << 16);
        lp[i >> 1] = (uint32_t)__bfloat16_as_ushort(l0) | ((uint32_t)__bfloat16_as_ushort(l1) << 16);
        __nv_bfloat16 x0 = __float2bfloat16(v[i]), x1 = __float2bfloat16(v[i + 1]);
        xp[i >> 1] = (uint32_t)__bfloat16_as_ushort(x0) | ((uint32_t)__bfloat16_as_ushort(x1) << 16);
    }
    const size_t ab = row * KE + b0;          // byte off = row*8320 + 32*tid : 16B aligned
    reinterpret_cast<uint4*>(g_Ahi + ab)[0] = make_uint4(hp[0], hp[1], hp[2], hp[3]);
    reinterpret_cast<uint4*>(g_Ahi + ab)[1] = make_uint4(hp[4], hp[5], hp[6], hp[7]);
    reinterpret_cast<uint4*>(g_Alo + ab)[0] = make_uint4(lp[0], lp[1], lp[2], lp[3]);
    reinterpret_cast<uint4*>(g_Alo + ab)[1] = make_uint4(lp[4], lp[5], lp[6], lp[7]);
    const size_t xb = row * D_IN + b0;
    reinterpret_cast<uint4*>(g_Xr + xb)[0] = make_uint4(xp[0], xp[1], xp[2], xp[3]);
    reinterpret_cast<uint4*>(g_Xr + xb)[1] = make_uint4(xp[4], xp[5], xp[6], xp[7]);

    if (tid >= 224) {  // zero pad cols 4128..4159
        size_t c = row * KE + D_IN + RANK + (tid - 224);
        g_Ahi[c] = __float2bfloat16(0.f);
        g_Alo[c] = __float2bfloat16(0.f);
    }
}

// ------------------------------------------------- K2: r = Xr @ la^T  -> A cols 4096..4127
__global__ void __launch_bounds__(256) lora_r_kernel() {
    __shared__ __align__(1024) char sm[16384 + 4096];
    const uint32_t xs = smem_u32(sm), ls = xs + 16384;
    const int tid = threadIdx.x, lane = tid & 31, warp = tid >> 5;
    const size_t m0 = (size_t)blockIdx.x * 128;

    float acc[4][4];
#pragma unroll
    for (int g = 0; g < 4; g++)
#pragma unroll
        for (int i = 0; i < 4; i++) acc[g][i] = 0.0f;

    for (int kc = 0; kc < 64; ++kc) {
        const int k0 = kc * 64;
#pragma unroll
        for (int i = 0; i < 4; ++i) {   // Xr tile 128x64 bf16
            int seg = tid + i * 256, r = seg >> 3, s = seg & 7;
            uint4 val = *reinterpret_cast<const uint4*>(g_Xr + (m0 + r) * D_IN + k0 + s * 8);
            *reinterpret_cast<uint4*>(sm + swz(r, s)) = val;
        }
        {   // la tile 32x64 bf16
            int r = tid >> 3, s = tid & 7;
            if (r < 32) {
                uint4 val = *reinterpret_cast<const uint4*>(g_la + (size_t)r * D_IN + k0 + s * 8);
                *reinterpret_cast<uint4*>(sm + 16384 + swz(r, s)) = val;
            }
        }
        __syncthreads();
#pragma unroll
        for (int ks = 0; ks < 4; ++ks) {
            uint32_t a[4], b0r[4], b1r[4];
            {
                int r = warp * 16 + (lane & 15);
                ldm_x4(a, xs + swz(r, ks * 2 + (lane >> 4)));
            }
            {
                int r = (lane & 7) + ((lane >> 4) << 3);
                int u = ks * 2 + ((lane >> 3) & 1);
                ldm_x4(b0r, ls + swz(r, u));
                ldm_x4(b1r, ls + swz(r + 16, u));
            }
            mma16816(acc[0], a, &b0r[0]);
            mma16816(acc[1], a, &b0r[2]);
            mma16816(acc[2], a, &b1r[0]);
            mma16816(acc[3], a, &b1r[2]);
        }
        __syncthreads();
    }
#pragma unroll
    for (int g = 0; g < 4; ++g) {
        int col = D_IN + g * 8 + (lane & 3) * 2;
        size_t r0 = m0 + warp * 16 + (lane >> 2), r1 = r0 + 8;
        __nv_bfloat16 h, l;
        split_bf16(acc[g][0], h, l); g_Ahi[r0 * KE + col] = h;     g_Alo[r0 * KE + col] = l;
        split_bf16(acc[g][1], h, l); g_Ahi[r0 * KE + col + 1] = h; g_Alo[r0 * KE + col + 1] = l;
        split_bf16(acc[g][2], h, l); g_Ahi[r1 * KE + col] = h;     g_Alo[r1 * KE + col] = l;
        split_bf16(acc[g][3], h, l); g_Ahi[r1 * KE + col + 1] = h; g_Alo[r1 * KE + col + 1] = l;
    }
}

// ------------------------------------------------- K3: main GEMM (3-pass bf16 split)
__global__ void __launch_bounds__(256, 1)
gemm_kernel(float* __restrict__ out, const float* __restrict__ bias) {
    extern __shared__ char smem[];
    const uint32_t sb = (smem_u32(smem) + 1023) & ~1023u;
    const uint32_t s0 = sb, s1 = sb + STAGE_BYTES;
    const int tid = threadIdx.x, lane = tid & 31, warp = tid >> 5;
    const int m_off = (warp & 3) * 32, n_off = (warp >> 2) * 64;
    const size_t n0 = (size_t)blockIdx.x * 128;   // N fast -> wave shares A tiles
    const size_t m0 = (size_t)blockIdx.y * 128;

    float acc[2][8][4];
#pragma unroll
    for (int mi = 0; mi < 2; mi++)
#pragma unroll
        for (int g = 0; g < 8; g++)
#pragma unroll
            for (int i = 0; i < 4; i++) acc[mi][g][i] = 0.0f;

    auto load_tile = [&](uint32_t dst, const __nv_bfloat16* src, size_t row0, int chunk) {
#pragma unroll
        for (int i = 0; i < 4; ++i) {
            int seg = tid + i * 256, r = seg >> 3, s = seg & 7;
            cp_async16(dst + swz(r, s), src + (row0 + r) * KE + (size_t)chunk * 64 + s * 8);
        }
    };
    auto load_stage = [&](int chunk, uint32_t st) {
        load_tile(st,         g_Ahi, m0, chunk);
        load_tile(st + 16384, g_Alo, m0, chunk);
        load_tile(st + 32768, g_Whi, n0, chunk);
        load_tile(st + 49152, g_Wlo, n0, chunk);
    };
    auto compute = [&](uint32_t st) {
#pragma unroll
        for (int ks = 0; ks < 4; ++ks) {
            uint32_t ah[2][4], al[2][4], bh[4][4], bl[4][4];
            const int rA = lane & 15;
            const int uA = ks * 2 + (lane >> 4);
#pragma unroll
            for (int mi = 0; mi < 2; ++mi) {
                int r = m_off + mi * 16 + rA;
                ldm_x4(ah[mi], st + swz(r, uA));
                ldm_x4(al[mi], st + 16384 + swz(r, uA));
            }
            const int rB = (lane & 7) + ((lane >> 4) << 3);
            const int uB = ks * 2 + ((lane >> 3) & 1);
#pragma unroll
            for (int j = 0; j < 4; ++j) {
                int r = n_off + j * 16 + rB;
                ldm_x4(bh[j], st + 32768 + swz(r, uB));
                ldm_x4(bl[j], st + 49152 + swz(r, uB));
            }
#pragma unroll
            for (int mi = 0; mi < 2; ++mi)
#pragma unroll
                for (int j = 0; j < 4; ++j) {
                    mma16816(acc[mi][2 * j],     ah[mi], &bh[j][0]);
                    mma16816(acc[mi][2 * j + 1], ah[mi], &bh[j][2]);
                    mma16816(acc[mi][2 * j],     al[mi], &bh[j][0]);
                    mma16816(acc[mi][2 * j + 1], al[mi], &bh[j][2]);
                    mma16816(acc[mi][2 * j],     ah[mi], &bl[j][0]);
                    mma16816(acc[mi][2 * j + 1], ah[mi], &bl[j][2]);
                }
        }
    };

    load_stage(0, s0);
    CP_COMMIT();
    for (int c = 0; c < NCHUNK; ++c) {
        const uint32_t cur = (c & 1) ? s1 : s0;
        if (c + 1 < NCHUNK) {
            load_stage(c + 1, ((c + 1) & 1) ? s1 : s0);
            CP_COMMIT();
            CP_WAIT_1();
        } else {
            CP_WAIT_0();
        }
        __syncthreads();
        compute(cur);
        __syncthreads();
    }

    // epilogue: +bias, fp32 out
#pragma unroll
    for (int mi = 0; mi < 2; ++mi) {
        size_t r0 = m0 + m_off + mi * 16 + (lane >> 2);
#pragma unroll
        for (int g = 0; g < 8; ++g) {
            size_t col = n0 + n_off + g * 8 + (lane & 3) * 2;
            float b0v = __ldg(bias + col), b1v = __ldg(bias + col + 1);
            float2 v0 = make_float2(acc[mi][g][0] + b0v, acc[mi][g][1] + b1v);
            float2 v1 = make_float2(acc[mi][g][2] + b0v, acc[mi][g][3] + b1v);
            *reinterpret_cast<float2*>(out + r0 * D_OUT + col) = v0;
            *reinterpret_cast<float2*>(out + (r0 + 8) * D_OUT + col) = v1;
        }
    }
}

// ---------------------------------------------------------------- launch
extern "C" void kernel_launch(void* const* d_in, const int* in_sizes, int n_in,
                              void* d_out, int out_size) {
    const float* x    = (const float*)d_in[0];
    const float* S_in = (const float*)d_in[1];
    // d_in[2] = H_block (Sylvester/sqrt(128), reproduced analytically)
    const float* w    = (const float*)d_in[3];
    const float* la   = (const float*)d_in[4];
    const float* lb   = (const float*)d_in[5];
    const float* bias = (const float*)d_in[6];
    float* out = (float*)d_out;

    cudaFuncSetAttribute(gemm_kernel, cudaFuncAttributeMaxDynamicSharedMemorySize, SMEM_DYN);

    prep_w_kernel<<<D_OUT + RANK, 256>>>(w, lb, la);
    rotate_quant_kernel<<<MROWS, 256>>>(x, S_in);
    lora_r_kernel<<<MROWS / 128, 256>>>();
    dim3 grid(D_OUT / 128, MROWS / 128);
    gemm_kernel<<<grid, 256, SMEM_DYN>>>(out, bias);
}

// round 12
// speedup vs baseline: 1.3241x; 1.3241x over previous
#include <cuda_runtime.h>
#include <cuda_bf16.h>
#include <cuda_fp16.h>
#include <cstdint>
#include <cstddef>

#define D_IN   4096
#define D_OUT  4096
#define MROWS  8192
#define RANK   32
#define KE     4160           // 4096 + 32 lora + 32 zero pad = 65*64
#define NCHUNK 65
#define STAGE_BYTES 49152     // Ahi 16K | Alo 16K | W 16K
#define NSTAGE 3
#define SMEM_DYN (NSTAGE * STAGE_BYTES + 1024)

__device__ __half        g_Ahi[(size_t)MROWS * KE];
__device__ __half        g_Alo[(size_t)MROWS * KE];
__device__ __half        g_W  [(size_t)D_OUT * KE];
__device__ __nv_bfloat16 g_Xr [(size_t)MROWS * D_IN];
__device__ __nv_bfloat16 g_la [(size_t)RANK  * D_IN];

// ---------------------------------------------------------------- helpers
__device__ __forceinline__ uint32_t smem_u32(const void* p) {
    uint32_t a;
    asm("{ .reg .u64 t; cvta.to.shared.u64 t, %1; cvt.u32.u64 %0, t; }" : "=r"(a) : "l"(p));
    return a;
}
__device__ __forceinline__ void cp_async16(uint32_t dst, const void* src) {
    asm volatile("cp.async.cg.shared.global [%0], [%1], 16;" :: "r"(dst), "l"(src));
}
#define CP_COMMIT() asm volatile("cp.async.commit_group;" ::: "memory")
#define CP_WAIT_1() asm volatile("cp.async.wait_group 1;" ::: "memory")
#define CP_WAIT_0() asm volatile("cp.async.wait_group 0;" ::: "memory")

__device__ __forceinline__ void ldm_x4(uint32_t* r, uint32_t addr) {
    asm volatile("ldmatrix.sync.aligned.m8n8.x4.shared.b16 {%0,%1,%2,%3}, [%4];"
        : "=r"(r[0]), "=r"(r[1]), "=r"(r[2]), "=r"(r[3]) : "r"(addr));
}
__device__ __forceinline__ void mma_bf16(float* c, const uint32_t* a, const uint32_t* b) {
    asm volatile("mma.sync.aligned.m16n8k16.row.col.f32.bf16.bf16.f32 "
        "{%0,%1,%2,%3}, {%4,%5,%6,%7}, {%8,%9}, {%0,%1,%2,%3};"
        : "+f"(c[0]), "+f"(c[1]), "+f"(c[2]), "+f"(c[3])
        : "r"(a[0]), "r"(a[1]), "r"(a[2]), "r"(a[3]), "r"(b[0]), "r"(b[1]));
}
__device__ __forceinline__ void mma_f16(float* c, const uint32_t* a, const uint32_t* b) {
    asm volatile("mma.sync.aligned.m16n8k16.row.col.f32.f16.f16.f32 "
        "{%0,%1,%2,%3}, {%4,%5,%6,%7}, {%8,%9}, {%0,%1,%2,%3};"
        : "+f"(c[0]), "+f"(c[1]), "+f"(c[2]), "+f"(c[3])
        : "r"(a[0]), "r"(a[1]), "r"(a[2]), "r"(a[3]), "r"(b[0]), "r"(b[1]));
}
__device__ __forceinline__ void split_fp16(float v, __half& h, __half& l) {
    h = __float2half(v);
    l = __float2half(v - __half2float(h));
}
// swizzled byte offset within a 128B-row tile: (row, 16B-unit)
__device__ __forceinline__ uint32_t swz(int r, int u) {
    return (uint32_t)(r * 128 + ((u ^ (r & 7)) * 16));
}

// ------------------------------------------------- K0: W -> fp16 (+lora_b fold) + la->bf16
__global__ void __launch_bounds__(256) prep_w_kernel(const float* __restrict__ w,
                                                     const float* __restrict__ lb,
                                                     const float* __restrict__ la) {
    const size_t b = blockIdx.x;
    if (b < D_OUT) {
        for (int c = threadIdx.x; c < KE; c += 256) {
            float v = 0.0f;
            if (c < D_IN) v = w[b * D_IN + c];
            else if (c < D_IN + RANK) v = lb[b * RANK + (c - D_IN)];
            g_W[b * KE + c] = __float2half(v);
        }
    } else {
        const size_t r = b - D_OUT;   // 0..31
        for (int c = threadIdx.x; c < D_IN; c += 256)
            g_la[r * D_IN + c] = __float2bfloat16(la[r * D_IN + c]);
    }
}

// ------------------------------------------------- K1: rotate + NVFP4 quant + fp16 split
__device__ __forceinline__ float quantize_one(float v, float scale) {
    float an = fabsf(v) / scale;
    float lvl;
    if      (an <= 0.25f) lvl = 0.0f;   // ties -> lower level (argmin-first)
    else if (an <= 0.75f) lvl = 0.5f;
    else if (an <= 1.25f) lvl = 1.0f;
    else if (an <= 1.75f) lvl = 1.5f;
    else if (an <= 2.5f)  lvl = 2.0f;
    else if (an <= 3.5f)  lvl = 3.0f;
    else if (an <= 5.0f)  lvl = 4.0f;
    else                  lvl = 6.0f;
    return copysignf(lvl * scale, v);
}

__global__ void __launch_bounds__(256) rotate_quant_kernel(const float* __restrict__ x,
                                                           const float* __restrict__ S_in) {
    __shared__ float row_sm[D_IN];
    const int tid = threadIdx.x;
    const size_t row = blockIdx.x;

    const float* xr = x + row * D_IN;
    for (int i = tid; i < D_IN; i += 256) row_sm[i] = xr[i] * S_in[i];

    // FWHT per 128-block (Sylvester order == reference H_block, unnormalized)
    for (int st = 0; st < 7; st++) {
        __syncthreads();
        const int h = 1 << st;
        for (int p = tid; p < 2048; p += 256) {
            int seg = p >> 6, pi = p & 63;
            int base = (seg << 7) + ((pi >> st) << (st + 1)) + (pi & (h - 1));
            float a = row_sm[base], b = row_sm[base + h];
            row_sm[base] = a + b;
            row_sm[base + h] = a - b;
        }
    }
    __syncthreads();

    const float HN = 0.08838834764831845f;  // fl32(1/sqrt(128))
    const int b0 = tid << 4;
    float v[16], amax = 0.0f;
#pragma unroll
    for (int i = 0; i < 16; i++) {
        v[i] = row_sm[b0 + i] * HN;
        amax = fmaxf(amax, fabsf(v[i]));
    }
    amax = fmaxf(amax, 1e-12f);
    const float scale = amax / 6.0f;

    uint32_t hp[8], lp[8], xp[8];
#pragma unroll
    for (int i = 0; i < 16; i += 2) {
        float q0 = quantize_one(v[i], scale), q1 = quantize_one(v[i + 1], scale);
        __half h0, l0, h1, l1;
        split_fp16(q0, h0, l0);
        split_fp16(q1, h1, l1);
        hp[i >> 1] = (uint32_t)__half_as_ushort(h0) | ((uint32_t)__half_as_ushort(h1) << 16);
        lp[i >> 1] = (uint32_t)__half_as_ushort(l0) | ((uint32_t)__half_as_ushort(l1) << 16);
        __nv_bfloat16 x0 = __float2bfloat16(v[i]), x1 = __float2bfloat16(v[i + 1]);
        xp[i >> 1] = (uint32_t)__bfloat16_as_ushort(x0) | ((uint32_t)__bfloat16_as_ushort(x1) << 16);
    }
    const size_t ab = row * KE + b0;          // byte off = row*8320 + 32*tid : 16B aligned
    reinterpret_cast<uint4*>(g_Ahi + ab)[0] = make_uint4(hp[0], hp[1], hp[2], hp[3]);
    reinterpret_cast<uint4*>(g_Ahi + ab)[1] = make_uint4(hp[4], hp[5], hp[6], hp[7]);
    reinterpret_cast<uint4*>(g_Alo + ab)[0] = make_uint4(lp[0], lp[1], lp[2], lp[3]);
    reinterpret_cast<uint4*>(g_Alo + ab)[1] = make_uint4(lp[4], lp[5], lp[6], lp[7]);
    const size_t xb = row * D_IN + b0;
    reinterpret_cast<uint4*>(g_Xr + xb)[0] = make_uint4(xp[0], xp[1], xp[2], xp[3]);
    reinterpret_cast<uint4*>(g_Xr + xb)[1] = make_uint4(xp[4], xp[5], xp[6], xp[7]);

    if (tid >= 224) {  // zero pad cols 4128..4159
        size_t c = row * KE + D_IN + RANK + (tid - 224);
        g_Ahi[c] = __ushort_as_half((unsigned short)0);
        g_Alo[c] = __ushort_as_half((unsigned short)0);
    }
}

// ------------------------------------------------- K2: r = Xr @ la^T  -> A cols 4096..4127
__global__ void __launch_bounds__(256) lora_r_kernel() {
    __shared__ __align__(1024) char sm[16384 + 4096];
    const uint32_t xs = smem_u32(sm), ls = xs + 16384;
    const int tid = threadIdx.x, lane = tid & 31, warp = tid >> 5;
    const size_t m0 = (size_t)blockIdx.x * 128;

    float acc[4][4];
#pragma unroll
    for (int g = 0; g < 4; g++)
#pragma unroll
        for (int i = 0; i < 4; i++) acc[g][i] = 0.0f;

    for (int kc = 0; kc < 64; ++kc) {
        const int k0 = kc * 64;
#pragma unroll
        for (int i = 0; i < 4; ++i) {   // Xr tile 128x64 bf16
            int seg = tid + i * 256, r = seg >> 3, s = seg & 7;
            uint4 val = *reinterpret_cast<const uint4*>(g_Xr + (m0 + r) * D_IN + k0 + s * 8);
            *reinterpret_cast<uint4*>(sm + swz(r, s)) = val;
        }
        {   // la tile 32x64 bf16
            int r = tid >> 3, s = tid & 7;
            if (r < 32) {
                uint4 val = *reinterpret_cast<const uint4*>(g_la + (size_t)r * D_IN + k0 + s * 8);
                *reinterpret_cast<uint4*>(sm + 16384 + swz(r, s)) = val;
            }
        }
        __syncthreads();
#pragma unroll
        for (int ks = 0; ks < 4; ++ks) {
            uint32_t a[4], b0r[4], b1r[4];
            {
                int r = warp * 16 + (lane & 15);
                ldm_x4(a, xs + swz(r, ks * 2 + (lane >> 4)));
            }
            {
                int r = (lane & 7) + ((lane >> 4) << 3);
                int u = ks * 2 + ((lane >> 3) & 1);
                ldm_x4(b0r, ls + swz(r, u));
                ldm_x4(b1r, ls + swz(r + 16, u));
            }
            mma_bf16(acc[0], a, &b0r[0]);
            mma_bf16(acc[1], a, &b0r[2]);
            mma_bf16(acc[2], a, &b1r[0]);
            mma_bf16(acc[3], a, &b1r[2]);
        }
        __syncthreads();
    }
#pragma unroll
    for (int g = 0; g < 4; ++g) {
        int col = D_IN + g * 8 + (lane & 3) * 2;
        size_t r0 = m0 + warp * 16 + (lane >> 2), r1 = r0 + 8;
        __half h, l;
        split_fp16(acc[g][0], h, l); g_Ahi[r0 * KE + col] = h;     g_Alo[r0 * KE + col] = l;
        split_fp16(acc[g][1], h, l); g_Ahi[r0 * KE + col + 1] = h; g_Alo[r0 * KE + col + 1] = l;
        split_fp16(acc[g][2], h, l); g_Ahi[r1 * KE + col] = h;     g_Alo[r1 * KE + col] = l;
        split_fp16(acc[g][3], h, l); g_Ahi[r1 * KE + col + 1] = h; g_Alo[r1 * KE + col + 1] = l;
    }
}

// ------------------------------------------------- K3: main GEMM (2-pass fp16 split)
__global__ void __launch_bounds__(256, 1)
gemm_kernel(float* __restrict__ out, const float* __restrict__ bias) {
    extern __shared__ char smem[];
    const uint32_t sb = (smem_u32(smem) + 1023) & ~1023u;
    const int tid = threadIdx.x, lane = tid & 31, warp = tid >> 5;
    const int m_off = (warp & 3) * 32, n_off = (warp >> 2) * 64;
    const size_t n0 = (size_t)blockIdx.x * 128;   // N fast -> wave shares A tiles
    const size_t m0 = (size_t)blockIdx.y * 128;

    float acc[2][8][4];
#pragma unroll
    for (int mi = 0; mi < 2; mi++)
#pragma unroll
        for (int g = 0; g < 8; g++)
#pragma unroll
            for (int i = 0; i < 4; i++) acc[mi][g][i] = 0.0f;

    auto stage_addr = [&](int c) { return sb + (uint32_t)(c % NSTAGE) * STAGE_BYTES; };

    auto load_tile = [&](uint32_t dst, const __half* src, size_t row0, int chunk) {
#pragma unroll
        for (int i = 0; i < 4; ++i) {
            int seg = tid + i * 256, r = seg >> 3, s = seg & 7;
            cp_async16(dst + swz(r, s), src + (row0 + r) * KE + (size_t)chunk * 64 + s * 8);
        }
    };
    auto load_stage = [&](int chunk, uint32_t st) {
        load_tile(st,         g_Ahi, m0, chunk);
        load_tile(st + 16384, g_Alo, m0, chunk);
        load_tile(st + 32768, g_W,   n0, chunk);
    };
    auto compute = [&](uint32_t st) {
#pragma unroll
        for (int ks = 0; ks < 4; ++ks) {
            uint32_t ah[2][4], al[2][4], bw[4][4];
            const int rA = lane & 15;
            const int uA = ks * 2 + (lane >> 4);
#pragma unroll
            for (int mi = 0; mi < 2; ++mi) {
                int r = m_off + mi * 16 + rA;
                ldm_x4(ah[mi], st + swz(r, uA));
                ldm_x4(al[mi], st + 16384 + swz(r, uA));
            }
            const int rB = (lane & 7) + ((lane >> 4) << 3);
            const int uB = ks * 2 + ((lane >> 3) & 1);
#pragma unroll
            for (int j = 0; j < 4; ++j) {
                int r = n_off + j * 16 + rB;
                ldm_x4(bw[j], st + 32768 + swz(r, uB));
            }
#pragma unroll
            for (int mi = 0; mi < 2; ++mi)
#pragma unroll
                for (int j = 0; j < 4; ++j) {
                    mma_f16(acc[mi][2 * j],     ah[mi], &bw[j][0]);
                    mma_f16(acc[mi][2 * j + 1], ah[mi], &bw[j][2]);
                    mma_f16(acc[mi][2 * j],     al[mi], &bw[j][0]);
                    mma_f16(acc[mi][2 * j + 1], al[mi], &bw[j][2]);
                }
        }
    };

    load_stage(0, stage_addr(0));
    CP_COMMIT();
    load_stage(1, stage_addr(1));
    CP_COMMIT();

    for (int c = 0; c < NCHUNK; ++c) {
        if (c == NCHUNK - 1) { CP_WAIT_0(); } else { CP_WAIT_1(); }
        __syncthreads();                       // stage c ready for all threads
        if (c + 2 < NCHUNK) {                  // prefetch into stage (c+2)%3 (free: computed at c-1)
            load_stage(c + 2, stage_addr(c + 2));
            CP_COMMIT();
        }
        compute(stage_addr(c));
        // next iteration's top __syncthreads (after wait) orders compute(c) before
        // any thread's loads overwrite stage c%3 (== stage (c+3)%3).
    }

    // epilogue: +bias, fp32 out
#pragma unroll
    for (int mi = 0; mi < 2; ++mi) {
        size_t r0 = m0 + m_off + mi * 16 + (lane >> 2);
#pragma unroll
        for (int g = 0; g < 8; ++g) {
            size_t col = n0 + n_off + g * 8 + (lane & 3) * 2;
            float b0v = __ldg(bias + col), b1v = __ldg(bias + col + 1);
            float2 v0 = make_float2(acc[mi][g][0] + b0v, acc[mi][g][1] + b1v);
            float2 v1 = make_float2(acc[mi][g][2] + b0v, acc[mi][g][3] + b1v);
            *reinterpret_cast<float2*>(out + r0 * D_OUT + col) = v0;
            *reinterpret_cast<float2*>(out + (r0 + 8) * D_OUT + col) = v1;
        }
    }
}

// ---------------------------------------------------------------- launch
extern "C" void kernel_launch(void* const* d_in, const int* in_sizes, int n_in,
                              void* d_out, int out_size) {
    const float* x    = (const float*)d_in[0];
    const float* S_in = (const float*)d_in[1];
    // d_in[2] = H_block (Sylvester/sqrt(128), reproduced analytically)
    const float* w    = (const float*)d_in[3];
    const float* la   = (const float*)d_in[4];
    const float* lb   = (const float*)d_in[5];
    const float* bias = (const float*)d_in[6];
    float* out = (float*)d_out;

    cudaFuncSetAttribute(gemm_kernel, cudaFuncAttributeMaxDynamicSharedMemorySize, SMEM_DYN);

    prep_w_kernel<<<D_OUT + RANK, 256>>>(w, lb, la);
    rotate_quant_kernel<<<MROWS, 256>>>(x, S_in);
    lora_r_kernel<<<MROWS / 128, 256>>>();
    dim3 grid(D_OUT / 128, MROWS / 128);
    gemm_kernel<<<grid, 256, SMEM_DYN>>>(out, bias);
}

// round 15
// speedup vs baseline: 2.2398x; 1.6916x over previous
#include <cuda_runtime.h>
#include <cuda_bf16.h>
#include <cuda_fp16.h>
#include <cstdint>
#include <cstddef>

#define D_IN   4096
#define D_OUT  4096
#define MROWS  8192
#define RANK   32
#define KE     4160           // 4096 + 32 lora + 32 zero pad = 65*64
#define NCHUNK 65
#define STAGE_BYTES 32768     // A 16K | W 16K
#define NSTAGE 3
#define SMEM_DYN (NSTAGE * STAGE_BYTES + 1024)

__device__ __half        g_A  [(size_t)MROWS * KE];
__device__ __half        g_W  [(size_t)D_OUT * KE];
__device__ __nv_bfloat16 g_Xr [(size_t)MROWS * D_IN];
__device__ __nv_bfloat16 g_la [(size_t)RANK  * D_IN];

// ---------------------------------------------------------------- helpers
__device__ __forceinline__ uint32_t smem_u32(const void* p) {
    uint32_t a;
    asm("{ .reg .u64 t; cvta.to.shared.u64 t, %1; cvt.u32.u64 %0, t; }" : "=r"(a) : "l"(p));
    return a;
}
__device__ __forceinline__ void cp_async16(uint32_t dst, const void* src) {
    asm volatile("cp.async.cg.shared.global [%0], [%1], 16;" :: "r"(dst), "l"(src));
}
#define CP_COMMIT() asm volatile("cp.async.commit_group;" ::: "memory")
#define CP_WAIT_2() asm volatile("cp.async.wait_group 2;" ::: "memory")
#define CP_WAIT_1() asm volatile("cp.async.wait_group 1;" ::: "memory")
#define CP_WAIT_0() asm volatile("cp.async.wait_group 0;" ::: "memory")

__device__ __forceinline__ void ldm_x4(uint32_t* r, uint32_t addr) {
    asm volatile("ldmatrix.sync.aligned.m8n8.x4.shared.b16 {%0,%1,%2,%3}, [%4];"
        : "=r"(r[0]), "=r"(r[1]), "=r"(r[2]), "=r"(r[3]) : "r"(addr));
}
__device__ __forceinline__ void mma_bf16(float* c, const uint32_t* a, const uint32_t* b) {
    asm volatile("mma.sync.aligned.m16n8k16.row.col.f32.bf16.bf16.f32 "
        "{%0,%1,%2,%3}, {%4,%5,%6,%7}, {%8,%9}, {%0,%1,%2,%3};"
        : "+f"(c[0]), "+f"(c[1]), "+f"(c[2]), "+f"(c[3])
        : "r"(a[0]), "r"(a[1]), "r"(a[2]), "r"(a[3]), "r"(b[0]), "r"(b[1]));
}
__device__ __forceinline__ void mma_f16(float* c, const uint32_t* a, const uint32_t* b) {
    asm volatile("mma.sync.aligned.m16n8k16.row.col.f32.f16.f16.f32 "
        "{%0,%1,%2,%3}, {%4,%5,%6,%7}, {%8,%9}, {%0,%1,%2,%3};"
        : "+f"(c[0]), "+f"(c[1]), "+f"(c[2]), "+f"(c[3])
        : "r"(a[0]), "r"(a[1]), "r"(a[2]), "r"(a[3]), "r"(b[0]), "r"(b[1]));
}
// swizzled byte offset within a 128B-row tile: (row, 16B-unit)
__device__ __forceinline__ uint32_t swz(int r, int u) {
    return (uint32_t)(r * 128 + ((u ^ (r & 7)) * 16));
}

// ------------------------------------------------- K0: W -> fp16 (+lora_b fold) + la->bf16
__global__ void __launch_bounds__(256) prep_w_kernel(const float* __restrict__ w,
                                                     const float* __restrict__ lb,
                                                     const float* __restrict__ la) {
    const size_t b = blockIdx.x;
    if (b < D_OUT) {
        for (int c = threadIdx.x; c < KE; c += 256) {
            float v = 0.0f;
            if (c < D_IN) v = w[b * D_IN + c];
            else if (c < D_IN + RANK) v = lb[b * RANK + (c - D_IN)];
            g_W[b * KE + c] = __float2half(v);
        }
    } else {
        const size_t r = b - D_OUT;   // 0..31
        for (int c = threadIdx.x; c < D_IN; c += 256)
            g_la[r * D_IN + c] = __float2bfloat16(la[r * D_IN + c]);
    }
}

// ------------------------------------------------- K1: rotate + NVFP4 quant -> fp16
__device__ __forceinline__ float quantize_one(float v, float scale) {
    float an = fabsf(v) / scale;
    float lvl;
    if      (an <= 0.25f) lvl = 0.0f;   // ties -> lower level (argmin-first)
    else if (an <= 0.75f) lvl = 0.5f;
    else if (an <= 1.25f) lvl = 1.0f;
    else if (an <= 1.75f) lvl = 1.5f;
    else if (an <= 2.5f)  lvl = 2.0f;
    else if (an <= 3.5f)  lvl = 3.0f;
    else if (an <= 5.0f)  lvl = 4.0f;
    else                  lvl = 6.0f;
    return copysignf(lvl * scale, v);
}

__global__ void __launch_bounds__(256) rotate_quant_kernel(const float* __restrict__ x,
                                                           const float* __restrict__ S_in) {
    __shared__ float row_sm[D_IN];
    const int tid = threadIdx.x;
    const size_t row = blockIdx.x;

    const float* xr = x + row * D_IN;
    for (int i = tid; i < D_IN; i += 256) row_sm[i] = xr[i] * S_in[i];

    // FWHT per 128-block (Sylvester order == reference H_block, unnormalized)
    for (int st = 0; st < 7; st++) {
        __syncthreads();
        const int h = 1 << st;
        for (int p = tid; p < 2048; p += 256) {
            int seg = p >> 6, pi = p & 63;
            int base = (seg << 7) + ((pi >> st) << (st + 1)) + (pi & (h - 1));
            float a = row_sm[base], b = row_sm[base + h];
            row_sm[base] = a + b;
            row_sm[base + h] = a - b;
        }
    }
    __syncthreads();

    const float HN = 0.08838834764831845f;  // fl32(1/sqrt(128))
    const int b0 = tid << 4;
    float v[16], amax = 0.0f;
#pragma unroll
    for (int i = 0; i < 16; i++) {
        v[i] = row_sm[b0 + i] * HN;
        amax = fmaxf(amax, fabsf(v[i]));
    }
    amax = fmaxf(amax, 1e-12f);
    const float scale = amax / 6.0f;

    uint32_t hp[8], xp[8];
#pragma unroll
    for (int i = 0; i < 16; i += 2) {
        float q0 = quantize_one(v[i], scale), q1 = quantize_one(v[i + 1], scale);
        __half h0 = __float2half(q0), h1 = __float2half(q1);
        hp[i >> 1] = (uint32_t)__half_as_ushort(h0) | ((uint32_t)__half_as_ushort(h1) << 16);
        __nv_bfloat16 x0 = __float2bfloat16(v[i]), x1 = __float2bfloat16(v[i + 1]);
        xp[i >> 1] = (uint32_t)__bfloat16_as_ushort(x0) | ((uint32_t)__bfloat16_as_ushort(x1) << 16);
    }
    const size_t ab = row * KE + b0;          // byte off = row*8320 + 32*tid : 16B aligned
    reinterpret_cast<uint4*>(g_A + ab)[0] = make_uint4(hp[0], hp[1], hp[2], hp[3]);
    reinterpret_cast<uint4*>(g_A + ab)[1] = make_uint4(hp[4], hp[5], hp[6], hp[7]);
    const size_t xb = row * D_IN + b0;
    reinterpret_cast<uint4*>(g_Xr + xb)[0] = make_uint4(xp[0], xp[1], xp[2], xp[3]);
    reinterpret_cast<uint4*>(g_Xr + xb)[1] = make_uint4(xp[4], xp[5], xp[6], xp[7]);

    if (tid >= 224) {  // zero pad cols 4128..4159
        size_t c = row * KE + D_IN + RANK + (tid - 224);
        g_A[c] = __ushort_as_half((unsigned short)0);
    }
}

// ------------------------------------------------- K2: r = Xr @ la^T  -> A cols 4096..4127
__global__ void __launch_bounds__(256) lora_r_kernel() {
    __shared__ __align__(1024) char sm[16384 + 4096];
    const uint32_t xs = smem_u32(sm), ls = xs + 16384;
    const int tid = threadIdx.x, lane = tid & 31, warp = tid >> 5;
    const size_t m0 = (size_t)blockIdx.x * 128;

    float acc[4][4];
#pragma unroll
    for (int g = 0; g < 4; g++)
#pragma unroll
        for (int i = 0; i < 4; i++) acc[g][i] = 0.0f;

    for (int kc = 0; kc < 64; ++kc) {
        const int k0 = kc * 64;
#pragma unroll
        for (int i = 0; i < 4; ++i) {   // Xr tile 128x64 bf16
            int seg = tid + i * 256, r = seg >> 3, s = seg & 7;
            uint4 val = *reinterpret_cast<const uint4*>(g_Xr + (m0 + r) * D_IN + k0 + s * 8);
            *reinterpret_cast<uint4*>(sm + swz(r, s)) = val;
        }
        {   // la tile 32x64 bf16
            int r = tid >> 3, s = tid & 7;
            if (r < 32) {
                uint4 val = *reinterpret_cast<const uint4*>(g_la + (size_t)r * D_IN + k0 + s * 8);
                *reinterpret_cast<uint4*>(sm + 16384 + swz(r, s)) = val;
            }
        }
        __syncthreads();
#pragma unroll
        for (int ks = 0; ks < 4; ++ks) {
            uint32_t a[4], b0r[4], b1r[4];
            {
                int r = warp * 16 + (lane & 15);
                ldm_x4(a, xs + swz(r, ks * 2 + (lane >> 4)));
            }
            {
                int r = (lane & 7) + ((lane >> 4) << 3);
                int u = ks * 2 + ((lane >> 3) & 1);
                ldm_x4(b0r, ls + swz(r, u));
                ldm_x4(b1r, ls + swz(r + 16, u));
            }
            mma_bf16(acc[0], a, &b0r[0]);
            mma_bf16(acc[1], a, &b0r[2]);
            mma_bf16(acc[2], a, &b1r[0]);
            mma_bf16(acc[3], a, &b1r[2]);
        }
        __syncthreads();
    }
#pragma unroll
    for (int g = 0; g < 4; ++g) {
        int col = D_IN + g * 8 + (lane & 3) * 2;
        size_t r0 = m0 + warp * 16 + (lane >> 2), r1 = r0 + 8;
        g_A[r0 * KE + col]     = __float2half(acc[g][0]);
        g_A[r0 * KE + col + 1] = __float2half(acc[g][1]);
        g_A[r1 * KE + col]     = __float2half(acc[g][2]);
        g_A[r1 * KE + col + 1] = __float2half(acc[g][3]);
    }
}

// ------------------------------------------------- K3: main GEMM (single-pass fp16)
__global__ void __launch_bounds__(256, 2)
gemm_kernel(float* __restrict__ out, const float* __restrict__ bias) {
    extern __shared__ char smem[];
    const uint32_t sb = (smem_u32(smem) + 1023) & ~1023u;
    const int tid = threadIdx.x, lane = tid & 31, warp = tid >> 5;
    const int m_off = (warp & 3) * 32, n_off = (warp >> 2) * 64;
    const size_t n0 = (size_t)blockIdx.x * 128;   // N fast -> wave shares A tiles
    const size_t m0 = (size_t)blockIdx.y * 128;

    float acc[2][8][4];
#pragma unroll
    for (int mi = 0; mi < 2; mi++)
#pragma unroll
        for (int g = 0; g < 8; g++)
#pragma unroll
            for (int i = 0; i < 4; i++) acc[mi][g][i] = 0.0f;

    auto stage_addr = [&](int c) { return sb + (uint32_t)(c % NSTAGE) * STAGE_BYTES; };

    auto load_tile = [&](uint32_t dst, const __half* src, size_t row0, int chunk) {
#pragma unroll
        for (int i = 0; i < 4; ++i) {
            int seg = tid + i * 256, r = seg >> 3, s = seg & 7;
            cp_async16(dst + swz(r, s), src + (row0 + r) * KE + (size_t)chunk * 64 + s * 8);
        }
    };
    auto load_stage = [&](int chunk, uint32_t st) {
        load_tile(st,         g_A, m0, chunk);
        load_tile(st + 16384, g_W, n0, chunk);
    };
    auto compute = [&](uint32_t st) {
#pragma unroll
        for (int ks = 0; ks < 4; ++ks) {
            uint32_t ah[2][4], bw[4][4];
            const int rA = lane & 15;
            const int uA = ks * 2 + (lane >> 4);
#pragma unroll
            for (int mi = 0; mi < 2; ++mi)
                ldm_x4(ah[mi], st + swz(m_off + mi * 16 + rA, uA));
            const int rB = (lane & 7) + ((lane >> 4) << 3);
            const int uB = ks * 2 + ((lane >> 3) & 1);
#pragma unroll
            for (int j = 0; j < 4; ++j)
                ldm_x4(bw[j], st + 16384 + swz(n_off + j * 16 + rB, uB));
#pragma unroll
            for (int mi = 0; mi < 2; ++mi)
#pragma unroll
                for (int j = 0; j < 4; ++j) {
                    mma_f16(acc[mi][2 * j],     ah[mi], &bw[j][0]);
                    mma_f16(acc[mi][2 * j + 1], ah[mi], &bw[j][2]);
                }
        }
    };

    load_stage(0, stage_addr(0));
    CP_COMMIT();
    load_stage(1, stage_addr(1));
    CP_COMMIT();
    load_stage(2, stage_addr(2));
    CP_COMMIT();

    for (int c = 0; c < NCHUNK; ++c) {
        // groups in flight cover chunks c .. min(c+2, NCHUNK-1); make stage c resident
        const int ahead = NCHUNK - 1 - c;
        if (ahead >= 2)      { CP_WAIT_2(); }
        else if (ahead == 1) { CP_WAIT_1(); }
        else                 { CP_WAIT_0(); }
        __syncthreads();                     // stage c visible to all warps
        compute(stage_addr(c));
        __syncthreads();                     // all warps done reading slot c%3
        if (c + 3 < NCHUNK) {                // now safe: refill slot (c+3)%3 == c%3
            load_stage(c + 3, stage_addr(c + 3));
            CP_COMMIT();                     // overlaps with compute(c+1), compute(c+2)
        }
    }

    // epilogue: +bias, fp32 out
#pragma unroll
    for (int mi = 0; mi < 2; ++mi) {
        size_t r0 = m0 + m_off + mi * 16 + (lane >> 2);
#pragma unroll
        for (int g = 0; g < 8; ++g) {
            size_t col = n0 + n_off + g * 8 + (lane & 3) * 2;
            float b0v = __ldg(bias + col), b1v = __ldg(bias + col + 1);
            float2 v0 = make_float2(acc[mi][g][0] + b0v, acc[mi][g][1] + b1v);
            float2 v1 = make_float2(acc[mi][g][2] + b0v, acc[mi][g][3] + b1v);
            *reinterpret_cast<float2*>(out + r0 * D_OUT + col) = v0;
            *reinterpret_cast<float2*>(out + (r0 + 8) * D_OUT + col) = v1;
        }
    }
}

// ---------------------------------------------------------------- launch
extern "C" void kernel_launch(void* const* d_in, const int* in_sizes, int n_in,
                              void* d_out, int out_size) {
    const float* x    = (const float*)d_in[0];
    const float* S_in = (const float*)d_in[1];
    // d_in[2] = H_block (Sylvester/sqrt(128), reproduced analytically)
    const float* w    = (const float*)d_in[3];
    const float* la   = (const float*)d_in[4];
    const float* lb   = (const float*)d_in[5];
    const float* bias = (const float*)d_in[6];
    float* out = (float*)d_out;

    cudaFuncSetAttribute(gemm_kernel, cudaFuncAttributeMaxDynamicSharedMemorySize, SMEM_DYN);

    prep_w_kernel<<<D_OUT + RANK, 256>>>(w, lb, la);
    rotate_quant_kernel<<<MROWS, 256>>>(x, S_in);
    lora_r_kernel<<<MROWS / 128, 256>>>();
    dim3 grid(D_OUT / 128, MROWS / 128);
    gemm_kernel<<<grid, 256, SMEM_DYN>>>(out, bias);
}

// round 16
// speedup vs baseline: 2.5029x; 1.1175x over previous
#include <cuda_runtime.h>
#include <cuda_bf16.h>
#include <cuda_fp16.h>
#include <cstdint>
#include <cstddef>

#define D_IN   4096
#define D_OUT  4096
#define MROWS  8192
#define RANK   32
#define KE     4160           // 4096 + 32 lora + 32 zero pad = 65*64
#define NCHUNK 65
#define STAGE_BYTES 32768     // A 16K | W 16K
#define NSTAGE 3
#define SMEM_DYN (NSTAGE * STAGE_BYTES + 1024)
#define KSPLIT 8

__device__ __half        g_A  [(size_t)MROWS * KE];
__device__ __half        g_W  [(size_t)D_OUT * KE];
__device__ __nv_bfloat16 g_Xr [(size_t)MROWS * D_IN];
__device__ __nv_bfloat16 g_la [(size_t)RANK  * D_IN];
__device__ float         g_Rp [KSPLIT][MROWS][RANK];   // lora partials (8 MB)

// ---------------------------------------------------------------- helpers
__device__ __forceinline__ uint32_t smem_u32(const void* p) {
    uint32_t a;
    asm("{ .reg .u64 t; cvta.to.shared.u64 t, %1; cvt.u32.u64 %0, t; }" : "=r"(a) : "l"(p));
    return a;
}
__device__ __forceinline__ void cp_async16(uint32_t dst, const void* src) {
    asm volatile("cp.async.cg.shared.global [%0], [%1], 16;" :: "r"(dst), "l"(src));
}
#define CP_COMMIT() asm volatile("cp.async.commit_group;" ::: "memory")
#define CP_WAIT_1() asm volatile("cp.async.wait_group 1;" ::: "memory")
#define CP_WAIT_0() asm volatile("cp.async.wait_group 0;" ::: "memory")

__device__ __forceinline__ void ldm_x4(uint32_t* r, uint32_t addr) {
    asm volatile("ldmatrix.sync.aligned.m8n8.x4.shared.b16 {%0,%1,%2,%3}, [%4];"
        : "=r"(r[0]), "=r"(r[1]), "=r"(r[2]), "=r"(r[3]) : "r"(addr));
}
__device__ __forceinline__ void mma_bf16(float* c, const uint32_t* a, const uint32_t* b) {
    asm volatile("mma.sync.aligned.m16n8k16.row.col.f32.bf16.bf16.f32 "
        "{%0,%1,%2,%3}, {%4,%5,%6,%7}, {%8,%9}, {%0,%1,%2,%3};"
        : "+f"(c[0]), "+f"(c[1]), "+f"(c[2]), "+f"(c[3])
        : "r"(a[0]), "r"(a[1]), "r"(a[2]), "r"(a[3]), "r"(b[0]), "r"(b[1]));
}
__device__ __forceinline__ void mma_f16(float* c, const uint32_t* a, const uint32_t* b) {
    asm volatile("mma.sync.aligned.m16n8k16.row.col.f32.f16.f16.f32 "
        "{%0,%1,%2,%3}, {%4,%5,%6,%7}, {%8,%9}, {%0,%1,%2,%3};"
        : "+f"(c[0]), "+f"(c[1]), "+f"(c[2]), "+f"(c[3])
        : "r"(a[0]), "r"(a[1]), "r"(a[2]), "r"(a[3]), "r"(b[0]), "r"(b[1]));
}
// swizzled byte offset within a 128B-row tile: (row, 16B-unit)
__device__ __forceinline__ uint32_t swz(int r, int u) {
    return (uint32_t)(r * 128 + ((u ^ (r & 7)) * 16));
}

// ------------------------------------------------- K0: fused prep
//   blocks [0, MROWS)                : rotate + NVFP4 quant -> g_A, g_Xr
//   blocks [MROWS, MROWS+D_OUT)      : W row -> fp16 (+lora_b fold)
//   blocks [MROWS+D_OUT, +RANK)      : la row -> bf16
__device__ __forceinline__ float quantize_one(float v, float scale) {
    float an = fabsf(v) / scale;
    float lvl;
    if      (an <= 0.25f) lvl = 0.0f;   // ties -> lower level (argmin-first)
    else if (an <= 0.75f) lvl = 0.5f;
    else if (an <= 1.25f) lvl = 1.0f;
    else if (an <= 1.75f) lvl = 1.5f;
    else if (an <= 2.5f)  lvl = 2.0f;
    else if (an <= 3.5f)  lvl = 3.0f;
    else if (an <= 5.0f)  lvl = 4.0f;
    else                  lvl = 6.0f;
    return copysignf(lvl * scale, v);
}

__global__ void __launch_bounds__(256) prep_kernel(const float* __restrict__ x,
                                                   const float* __restrict__ S_in,
                                                   const float* __restrict__ w,
                                                   const float* __restrict__ lb,
                                                   const float* __restrict__ la) {
    __shared__ float row_sm[D_IN];
    const int tid = threadIdx.x;
    const size_t bid = blockIdx.x;

    if (bid >= MROWS) {
        if (bid < MROWS + D_OUT) {
            const size_t b = bid - MROWS;
            for (int c = tid; c < KE; c += 256) {
                float v = 0.0f;
                if (c < D_IN) v = w[b * D_IN + c];
                else if (c < D_IN + RANK) v = lb[b * RANK + (c - D_IN)];
                g_W[b * KE + c] = __float2half(v);
            }
        } else {
            const size_t r = bid - MROWS - D_OUT;   // 0..31
            for (int c = tid; c < D_IN; c += 256)
                g_la[r * D_IN + c] = __float2bfloat16(la[r * D_IN + c]);
        }
        return;
    }

    const size_t row = bid;
    const float* xr = x + row * D_IN;
    for (int i = tid; i < D_IN; i += 256) row_sm[i] = xr[i] * S_in[i];

    // FWHT per 128-block (Sylvester order == reference H_block, unnormalized)
    for (int st = 0; st < 7; st++) {
        __syncthreads();
        const int h = 1 << st;
        for (int p = tid; p < 2048; p += 256) {
            int seg = p >> 6, pi = p & 63;
            int base = (seg << 7) + ((pi >> st) << (st + 1)) + (pi & (h - 1));
            float a = row_sm[base], b = row_sm[base + h];
            row_sm[base] = a + b;
            row_sm[base + h] = a - b;
        }
    }
    __syncthreads();

    const float HN = 0.08838834764831845f;  // fl32(1/sqrt(128))
    const int b0 = tid << 4;
    float v[16], amax = 0.0f;
#pragma unroll
    for (int i = 0; i < 16; i++) {
        v[i] = row_sm[b0 + i] * HN;
        amax = fmaxf(amax, fabsf(v[i]));
    }
    amax = fmaxf(amax, 1e-12f);
    const float scale = amax / 6.0f;

    uint32_t hp[8], xp[8];
#pragma unroll
    for (int i = 0; i < 16; i += 2) {
        float q0 = quantize_one(v[i], scale), q1 = quantize_one(v[i + 1], scale);
        __half h0 = __float2half(q0), h1 = __float2half(q1);
        hp[i >> 1] = (uint32_t)__half_as_ushort(h0) | ((uint32_t)__half_as_ushort(h1) << 16);
        __nv_bfloat16 x0 = __float2bfloat16(v[i]), x1 = __float2bfloat16(v[i + 1]);
        xp[i >> 1] = (uint32_t)__bfloat16_as_ushort(x0) | ((uint32_t)__bfloat16_as_ushort(x1) << 16);
    }
    const size_t ab = row * KE + b0;          // byte off = row*8320 + 32*tid : 16B aligned
    reinterpret_cast<uint4*>(g_A + ab)[0] = make_uint4(hp[0], hp[1], hp[2], hp[3]);
    reinterpret_cast<uint4*>(g_A + ab)[1] = make_uint4(hp[4], hp[5], hp[6], hp[7]);
    const size_t xb = row * D_IN + b0;
    reinterpret_cast<uint4*>(g_Xr + xb)[0] = make_uint4(xp[0], xp[1], xp[2], xp[3]);
    reinterpret_cast<uint4*>(g_Xr + xb)[1] = make_uint4(xp[4], xp[5], xp[6], xp[7]);

    if (tid >= 224) {  // zero pad cols 4128..4159
        size_t c = row * KE + D_IN + RANK + (tid - 224);
        g_A[c] = __ushort_as_half((unsigned short)0);
    }
}

// ------------------------------------------------- K1: lora partials (K-split 8)
__global__ void __launch_bounds__(256) lora_r_kernel() {
    __shared__ __align__(1024) char sm[16384 + 4096];
    const uint32_t xs = smem_u32(sm), ls = xs + 16384;
    const int tid = threadIdx.x, lane = tid & 31, warp = tid >> 5;
    const size_t m0 = (size_t)blockIdx.x * 128;
    const int kz = blockIdx.y;                 // 0..7, covers kc in [kz*8, kz*8+8)

    float acc[4][4];
#pragma unroll
    for (int g = 0; g < 4; g++)
#pragma unroll
        for (int i = 0; i < 4; i++) acc[g][i] = 0.0f;

    for (int kc = kz * 8; kc < kz * 8 + 8; ++kc) {
        const int k0 = kc * 64;
#pragma unroll
        for (int i = 0; i < 4; ++i) {   // Xr tile 128x64 bf16
            int seg = tid + i * 256, r = seg >> 3, s = seg & 7;
            uint4 val = *reinterpret_cast<const uint4*>(g_Xr + (m0 + r) * D_IN + k0 + s * 8);
            *reinterpret_cast<uint4*>(sm + swz(r, s)) = val;
        }
        {   // la tile 32x64 bf16
            int r = tid >> 3, s = tid & 7;
            if (r < 32) {
                uint4 val = *reinterpret_cast<const uint4*>(g_la + (size_t)r * D_IN + k0 + s * 8);
                *reinterpret_cast<uint4*>(sm + 16384 + swz(r, s)) = val;
            }
        }
        __syncthreads();
#pragma unroll
        for (int ks = 0; ks < 4; ++ks) {
            uint32_t a[4], b0r[4], b1r[4];
            {
                int r = warp * 16 + (lane & 15);
                ldm_x4(a, xs + swz(r, ks * 2 + (lane >> 4)));
            }
            {
                int r = (lane & 7) + ((lane >> 4) << 3);
                int u = ks * 2 + ((lane >> 3) & 1);
                ldm_x4(b0r, ls + swz(r, u));
                ldm_x4(b1r, ls + swz(r + 16, u));
            }
            mma_bf16(acc[0], a, &b0r[0]);
            mma_bf16(acc[1], a, &b0r[2]);
            mma_bf16(acc[2], a, &b1r[0]);
            mma_bf16(acc[3], a, &b1r[2]);
        }
        __syncthreads();
    }
#pragma unroll
    for (int g = 0; g < 4; ++g) {
        int col = g * 8 + (lane & 3) * 2;
        size_t r0 = m0 + warp * 16 + (lane >> 2), r1 = r0 + 8;
        g_Rp[kz][r0][col]     = acc[g][0];
        g_Rp[kz][r0][col + 1] = acc[g][1];
        g_Rp[kz][r1][col]     = acc[g][2];
        g_Rp[kz][r1][col + 1] = acc[g][3];
    }
}

// ------------------------------------------------- K2: fold partials -> g_A cols 4096..4127
__global__ void __launch_bounds__(256) lora_fold_kernel() {
    const size_t idx = (size_t)blockIdx.x * 256 + threadIdx.x;   // over MROWS*RANK
    const size_t row = idx >> 5;
    const int rank = (int)(idx & 31);
    float s = 0.0f;
#pragma unroll
    for (int kz = 0; kz < KSPLIT; ++kz) s += g_Rp[kz][row][rank];
    g_A[row * KE + D_IN + rank] = __float2half(s);
}

// ------------------------------------------------- K3: main GEMM (single-pass fp16)
__global__ void __launch_bounds__(256, 2)
gemm_kernel(float* __restrict__ out, const float* __restrict__ bias) {
    extern __shared__ char smem[];
    const uint32_t sb = (smem_u32(smem) + 1023) & ~1023u;
    const int tid = threadIdx.x, lane = tid & 31, warp = tid >> 5;
    const int m_off = (warp & 3) * 32, n_off = (warp >> 2) * 64;
    const size_t n0 = (size_t)blockIdx.x * 128;   // N fast -> wave shares A tiles
    const size_t m0 = (size_t)blockIdx.y * 128;

    float acc[2][8][4];
#pragma unroll
    for (int mi = 0; mi < 2; mi++)
#pragma unroll
        for (int g = 0; g < 8; g++)
#pragma unroll
            for (int i = 0; i < 4; i++) acc[mi][g][i] = 0.0f;

    auto stage_addr = [&](int c) { return sb + (uint32_t)(c % NSTAGE) * STAGE_BYTES; };

    auto load_tile = [&](uint32_t dst, const __half* src, size_t row0, int chunk) {
#pragma unroll
        for (int i = 0; i < 4; ++i) {
            int seg = tid + i * 256, r = seg >> 3, s = seg & 7;
            cp_async16(dst + swz(r, s), src + (row0 + r) * KE + (size_t)chunk * 64 + s * 8);
        }
    };
    auto load_stage = [&](int chunk, uint32_t st) {
        load_tile(st,         g_A, m0, chunk);
        load_tile(st + 16384, g_W, n0, chunk);
    };
    auto compute = [&](uint32_t st) {
#pragma unroll
        for (int ks = 0; ks < 4; ++ks) {
            uint32_t ah[2][4], bw[4][4];
            const int rA = lane & 15;
            const int uA = ks * 2 + (lane >> 4);
#pragma unroll
            for (int mi = 0; mi < 2; ++mi)
                ldm_x4(ah[mi], st + swz(m_off + mi * 16 + rA, uA));
            const int rB = (lane & 7) + ((lane >> 4) << 3);
            const int uB = ks * 2 + ((lane >> 3) & 1);
#pragma unroll
            for (int j = 0; j < 4; ++j)
                ldm_x4(bw[j], st + 16384 + swz(n_off + j * 16 + rB, uB));
#pragma unroll
            for (int mi = 0; mi < 2; ++mi)
#pragma unroll
                for (int j = 0; j < 4; ++j) {
                    mma_f16(acc[mi][2 * j],     ah[mi], &bw[j][0]);
                    mma_f16(acc[mi][2 * j + 1], ah[mi], &bw[j][2]);
                }
        }
    };

    load_stage(0, stage_addr(0));
    CP_COMMIT();
    load_stage(1, stage_addr(1));
    CP_COMMIT();

    // single-barrier 3-stage pipeline, prefetch distance 2:
    //   load(c+2) targets slot (c+2)%3 == (c-1)%3 -- every warp has finished
    //   compute(c-1) before passing this iteration's barrier.
    for (int c = 0; c < NCHUNK; ++c) {
        if (c < NCHUNK - 1) { CP_WAIT_1(); } else { CP_WAIT_0(); }
        __syncthreads();                      // stage c resident; compute(c-1) done by all
        if (c + 2 < NCHUNK) {
            load_stage(c + 2, stage_addr(c + 2));
            CP_COMMIT();                      // DMA overlaps compute(c) and compute(c+1)
        }
        compute(stage_addr(c));
    }

    // epilogue: +bias, fp32 out
#pragma unroll
    for (int mi = 0; mi < 2; ++mi) {
        size_t r0 = m0 + m_off + mi * 16 + (lane >> 2);
#pragma unroll
        for (int g = 0; g < 8; ++g) {
            size_t col = n0 + n_off + g * 8 + (lane & 3) * 2;
            float b0v = __ldg(bias + col), b1v = __ldg(bias + col + 1);
            float2 v0 = make_float2(acc[mi][g][0] + b0v, acc[mi][g][1] + b1v);
            float2 v1 = make_float2(acc[mi][g][2] + b0v, acc[mi][g][3] + b1v);
            *reinterpret_cast<float2*>(out + r0 * D_OUT + col) = v0;
            *reinterpret_cast<float2*>(out + (r0 + 8) * D_OUT + col) = v1;
        }
    }
}

// ---------------------------------------------------------------- launch
extern "C" void kernel_launch(void* const* d_in, const int* in_sizes, int n_in,
                              void* d_out, int out_size) {
    const float* x    = (const float*)d_in[0];
    const float* S_in = (const float*)d_in[1];
    // d_in[2] = H_block (Sylvester/sqrt(128), reproduced analytically)
    const float* w    = (const float*)d_in[3];
    const float* la   = (const float*)d_in[4];
    const float* lb   = (const float*)d_in[5];
    const float* bias = (const float*)d_in[6];
    float* out = (float*)d_out;

    cudaFuncSetAttribute(gemm_kernel, cudaFuncAttributeMaxDynamicSharedMemorySize, SMEM_DYN);

    prep_kernel<<<MROWS + D_OUT + RANK, 256>>>(x, S_in, w, lb, la);
    dim3 lgrid(MROWS / 128, KSPLIT);
    lora_r_kernel<<<lgrid, 256>>>();
    lora_fold_kernel<<<(MROWS * RANK) / 256, 256>>>();
    dim3 grid(D_OUT / 128, MROWS / 128);
    gemm_kernel<<<grid, 256, SMEM_DYN>>>(out, bias);
}

// round 17
// speedup vs baseline: 2.8623x; 1.1436x over previous
#include <cuda_runtime.h>
#include <cuda_bf16.h>
#include <cuda_fp16.h>
#include <cstdint>
#include <cstddef>

#define D_IN   4096
#define D_OUT  4096
#define MROWS  8192
#define RANK   32
#define KE     4160           // 4096 + 32 lora + 32 zero pad = 65*64
#define NCHUNK 65
#define STAGE_BYTES 32768     // A 16K | W 16K
#define NSTAGE 3
#define SMEM_DYN (NSTAGE * STAGE_BYTES + 1024)
#define KSPLIT 8

__device__ __half        g_A  [(size_t)MROWS * KE];
__device__ __half        g_W  [(size_t)D_OUT * KE];
__device__ __nv_bfloat16 g_Xr [(size_t)MROWS * D_IN];
__device__ __nv_bfloat16 g_la [(size_t)RANK  * D_IN];
__device__ float         g_Rp [KSPLIT][MROWS][RANK];   // lora partials (8 MB)

// ---------------------------------------------------------------- helpers
__device__ __forceinline__ uint32_t smem_u32(const void* p) {
    uint32_t a;
    asm("{ .reg .u64 t; cvta.to.shared.u64 t, %1; cvt.u32.u64 %0, t; }" : "=r"(a) : "l"(p));
    return a;
}
__device__ __forceinline__ void cp_async16(uint32_t dst, const void* src) {
    asm volatile("cp.async.cg.shared.global [%0], [%1], 16;" :: "r"(dst), "l"(src));
}
#define CP_COMMIT() asm volatile("cp.async.commit_group;" ::: "memory")
#define CP_WAIT_1() asm volatile("cp.async.wait_group 1;" ::: "memory")
#define CP_WAIT_0() asm volatile("cp.async.wait_group 0;" ::: "memory")

__device__ __forceinline__ void ldm_x4(uint32_t* r, uint32_t addr) {
    asm volatile("ldmatrix.sync.aligned.m8n8.x4.shared.b16 {%0,%1,%2,%3}, [%4];"
        : "=r"(r[0]), "=r"(r[1]), "=r"(r[2]), "=r"(r[3]) : "r"(addr));
}
__device__ __forceinline__ void mma_bf16(float* c, const uint32_t* a, const uint32_t* b) {
    asm volatile("mma.sync.aligned.m16n8k16.row.col.f32.bf16.bf16.f32 "
        "{%0,%1,%2,%3}, {%4,%5,%6,%7}, {%8,%9}, {%0,%1,%2,%3};"
        : "+f"(c[0]), "+f"(c[1]), "+f"(c[2]), "+f"(c[3])
        : "r"(a[0]), "r"(a[1]), "r"(a[2]), "r"(a[3]), "r"(b[0]), "r"(b[1]));
}
__device__ __forceinline__ void mma_f16(float* c, const uint32_t* a, const uint32_t* b) {
    asm volatile("mma.sync.aligned.m16n8k16.row.col.f32.f16.f16.f32 "
        "{%0,%1,%2,%3}, {%4,%5,%6,%7}, {%8,%9}, {%0,%1,%2,%3};"
        : "+f"(c[0]), "+f"(c[1]), "+f"(c[2]), "+f"(c[3])
        : "r"(a[0]), "r"(a[1]), "r"(a[2]), "r"(a[3]), "r"(b[0]), "r"(b[1]));
}
// swizzled byte offset within a 128B-row tile: (row, 16B-unit)
__device__ __forceinline__ uint32_t swz(int r, int u) {
    return (uint32_t)(r * 128 + ((u ^ (r & 7)) * 16));
}

// ------------------------------------------------- K0: fused prep (no smem, no barriers)
//   blocks [0, MROWS)                : rotate (register FWHT) + NVFP4 quant -> g_A, g_Xr
//   blocks [MROWS, MROWS+D_OUT)      : W row -> fp16 (+lora_b fold)
//   blocks [MROWS+D_OUT, +RANK)      : la row -> bf16
__device__ __forceinline__ float quantize_one(float v, float scale) {
    float an = fabsf(v) / scale;
    float lvl;
    if      (an <= 0.25f) lvl = 0.0f;   // ties -> lower level (argmin-first)
    else if (an <= 0.75f) lvl = 0.5f;
    else if (an <= 1.25f) lvl = 1.0f;
    else if (an <= 1.75f) lvl = 1.5f;
    else if (an <= 2.5f)  lvl = 2.0f;
    else if (an <= 3.5f)  lvl = 3.0f;
    else if (an <= 5.0f)  lvl = 4.0f;
    else                  lvl = 6.0f;
    return copysignf(lvl * scale, v);
}

__global__ void __launch_bounds__(256) prep_kernel(const float* __restrict__ x,
                                                   const float* __restrict__ S_in,
                                                   const float* __restrict__ w,
                                                   const float* __restrict__ lb,
                                                   const float* __restrict__ la) {
    const int tid = threadIdx.x;
    const size_t bid = blockIdx.x;

    if (bid >= MROWS) {
        if (bid < MROWS + D_OUT) {
            const size_t b = bid - MROWS;
            const float* wr = w + b * D_IN;
            // cols 0..4095 vectorized: 8 floats -> 8 halves per step
            for (int c = tid * 8; c < D_IN; c += 256 * 8) {
                float4 f0 = *reinterpret_cast<const float4*>(wr + c);
                float4 f1 = *reinterpret_cast<const float4*>(wr + c + 4);
                __half2 h0 = __floats2half2_rn(f0.x, f0.y);
                __half2 h1 = __floats2half2_rn(f0.z, f0.w);
                __half2 h2 = __floats2half2_rn(f1.x, f1.y);
                __half2 h3 = __floats2half2_rn(f1.z, f1.w);
                uint4 o;
                o.x = *reinterpret_cast<uint32_t*>(&h0);
                o.y = *reinterpret_cast<uint32_t*>(&h1);
                o.z = *reinterpret_cast<uint32_t*>(&h2);
                o.w = *reinterpret_cast<uint32_t*>(&h3);
                *reinterpret_cast<uint4*>(g_W + b * KE + c) = o;
            }
            if (tid < 64) {  // cols 4096..4127 = lora_b, 4128..4159 = 0
                float v = (tid < RANK) ? lb[b * RANK + tid] : 0.0f;
                g_W[b * KE + D_IN + tid] = __float2half(v);
            }
        } else {
            const size_t r = bid - MROWS - D_OUT;   // 0..31
            for (int c = tid; c < D_IN; c += 256)
                g_la[r * D_IN + c] = __float2bfloat16(la[r * D_IN + c]);
        }
        return;
    }

    // ---- rotate row: thread owns contiguous 16-elem slice; 128-block = 8 lanes
    const size_t row = bid;
    const int lane = tid & 31;
    const int b0 = tid << 4;
    const float* xr = x + row * D_IN + b0;
    const float* sr = S_in + b0;

    float v[16];
#pragma unroll
    for (int i = 0; i < 16; i += 4) {
        float4 xv = *reinterpret_cast<const float4*>(xr + i);
        float4 sv = *reinterpret_cast<const float4*>(sr + i);
        v[i + 0] = xv.x * sv.x;
        v[i + 1] = xv.y * sv.y;
        v[i + 2] = xv.z * sv.z;
        v[i + 3] = xv.w * sv.w;
    }

    // FWHT stages 0..3: intra-thread (element bits 0..3)
#pragma unroll
    for (int st = 0; st < 4; ++st) {
        const int h = 1 << st;
#pragma unroll
        for (int p = 0; p < 8; ++p) {
            int i = ((p >> st) << (st + 1)) + (p & (h - 1));
            float a = v[i], b = v[i + h];
            v[i] = a + b;
            v[i + h] = a - b;
        }
    }
    // FWHT stages 4..6: cross-thread within the 8-lane group (lane bits 0..2)
#pragma unroll
    for (int st = 0; st < 3; ++st) {
        const int d = 1 << st;
        const bool up = (lane >> st) & 1;
#pragma unroll
        for (int i = 0; i < 16; ++i) {
            float pv = __shfl_xor_sync(0xffffffffu, v[i], d);
            v[i] = up ? (pv - v[i]) : (v[i] + pv);
        }
    }

    // normalize + NVFP4 fake quant (per-thread = per-16-block)
    const float HN = 0.08838834764831845f;  // fl32(1/sqrt(128))
    float amax = 0.0f;
#pragma unroll
    for (int i = 0; i < 16; i++) {
        v[i] *= HN;
        amax = fmaxf(amax, fabsf(v[i]));
    }
    amax = fmaxf(amax, 1e-12f);
    const float scale = amax / 6.0f;

    uint32_t hp[8], xp[8];
#pragma unroll
    for (int i = 0; i < 16; i += 2) {
        float q0 = quantize_one(v[i], scale), q1 = quantize_one(v[i + 1], scale);
        __half h0 = __float2half(q0), h1 = __float2half(q1);
        hp[i >> 1] = (uint32_t)__half_as_ushort(h0) | ((uint32_t)__half_as_ushort(h1) << 16);
        __nv_bfloat16 x0 = __float2bfloat16(v[i]), x1 = __float2bfloat16(v[i + 1]);
        xp[i >> 1] = (uint32_t)__bfloat16_as_ushort(x0) | ((uint32_t)__bfloat16_as_ushort(x1) << 16);
    }
    const size_t ab = row * KE + b0;          // byte off = row*8320 + 32*tid : 16B aligned
    reinterpret_cast<uint4*>(g_A + ab)[0] = make_uint4(hp[0], hp[1], hp[2], hp[3]);
    reinterpret_cast<uint4*>(g_A + ab)[1] = make_uint4(hp[4], hp[5], hp[6], hp[7]);
    const size_t xb = row * D_IN + b0;
    reinterpret_cast<uint4*>(g_Xr + xb)[0] = make_uint4(xp[0], xp[1], xp[2], xp[3]);
    reinterpret_cast<uint4*>(g_Xr + xb)[1] = make_uint4(xp[4], xp[5], xp[6], xp[7]);

    if (tid >= 224) {  // zero pad cols 4128..4159
        size_t c = row * KE + D_IN + RANK + (tid - 224);
        g_A[c] = __ushort_as_half((unsigned short)0);
    }
}

// ------------------------------------------------- K1: lora partials (K-split 8)
__global__ void __launch_bounds__(256) lora_r_kernel() {
    __shared__ __align__(1024) char sm[16384 + 4096];
    const uint32_t xs = smem_u32(sm), ls = xs + 16384;
    const int tid = threadIdx.x, lane = tid & 31, warp = tid >> 5;
    const size_t m0 = (size_t)blockIdx.x * 128;
    const int kz = blockIdx.y;                 // 0..7, covers kc in [kz*8, kz*8+8)

    float acc[4][4];
#pragma unroll
    for (int g = 0; g < 4; g++)
#pragma unroll
        for (int i = 0; i < 4; i++) acc[g][i] = 0.0f;

    for (int kc = kz * 8; kc < kz * 8 + 8; ++kc) {
        const int k0 = kc * 64;
#pragma unroll
        for (int i = 0; i < 4; ++i) {   // Xr tile 128x64 bf16
            int seg = tid + i * 256, r = seg >> 3, s = seg & 7;
            uint4 val = *reinterpret_cast<const uint4*>(g_Xr + (m0 + r) * D_IN + k0 + s * 8);
            *reinterpret_cast<uint4*>(sm + swz(r, s)) = val;
        }
        {   // la tile 32x64 bf16
            int r = tid >> 3, s = tid & 7;
            if (r < 32) {
                uint4 val = *reinterpret_cast<const uint4*>(g_la + (size_t)r * D_IN + k0 + s * 8);
                *reinterpret_cast<uint4*>(sm + 16384 + swz(r, s)) = val;
            }
        }
        __syncthreads();
#pragma unroll
        for (int ks = 0; ks < 4; ++ks) {
            uint32_t a[4], b0r[4], b1r[4];
            {
                int r = warp * 16 + (lane & 15);
                ldm_x4(a, xs + swz(r, ks * 2 + (lane >> 4)));
            }
            {
                int r = (lane & 7) + ((lane >> 4) << 3);
                int u = ks * 2 + ((lane >> 3) & 1);
                ldm_x4(b0r, ls + swz(r, u));
                ldm_x4(b1r, ls + swz(r + 16, u));
            }
            mma_bf16(acc[0], a, &b0r[0]);
            mma_bf16(acc[1], a, &b0r[2]);
            mma_bf16(acc[2], a, &b1r[0]);
            mma_bf16(acc[3], a, &b1r[2]);
        }
        __syncthreads();
    }
#pragma unroll
    for (int g = 0; g < 4; ++g) {
        int col = g * 8 + (lane & 3) * 2;
        size_t r0 = m0 + warp * 16 + (lane >> 2), r1 = r0 + 8;
        g_Rp[kz][r0][col]     = acc[g][0];
        g_Rp[kz][r0][col + 1] = acc[g][1];
        g_Rp[kz][r1][col]     = acc[g][2];
        g_Rp[kz][r1][col + 1] = acc[g][3];
    }
}

// ------------------------------------------------- K2: fold partials -> g_A cols 4096..4127
__global__ void __launch_bounds__(256) lora_fold_kernel() {
    const size_t idx = (size_t)blockIdx.x * 256 + threadIdx.x;   // over MROWS*RANK
    const size_t row = idx >> 5;
    const int rank = (int)(idx & 31);
    float s = 0.0f;
#pragma unroll
    for (int kz = 0; kz < KSPLIT; ++kz) s += g_Rp[kz][row][rank];
    g_A[row * KE + D_IN + rank] = __float2half(s);
}

// ------------------------------------------------- K3: main GEMM (single-pass fp16)
__global__ void __launch_bounds__(256, 2)
gemm_kernel(float* __restrict__ out, const float* __restrict__ bias) {
    extern __shared__ char smem[];
    const uint32_t sb = (smem_u32(smem) + 1023) & ~1023u;
    const int tid = threadIdx.x, lane = tid & 31, warp = tid >> 5;
    const int m_off = (warp & 3) * 32, n_off = (warp >> 2) * 64;
    const size_t n0 = (size_t)blockIdx.x * 128;   // N fast -> wave shares A tiles
    const size_t m0 = (size_t)blockIdx.y * 128;

    float acc[2][8][4];
#pragma unroll
    for (int mi = 0; mi < 2; mi++)
#pragma unroll
        for (int g = 0; g < 8; g++)
#pragma unroll
            for (int i = 0; i < 4; i++) acc[mi][g][i] = 0.0f;

    auto stage_addr = [&](int c) { return sb + (uint32_t)(c % NSTAGE) * STAGE_BYTES; };

    auto load_tile = [&](uint32_t dst, const __half* src, size_t row0, int chunk) {
#pragma unroll
        for (int i = 0; i < 4; ++i) {
            int seg = tid + i * 256, r = seg >> 3, s = seg & 7;
            cp_async16(dst + swz(r, s), src + (row0 + r) * KE + (size_t)chunk * 64 + s * 8);
        }
    };
    auto load_stage = [&](int chunk, uint32_t st) {
        load_tile(st,         g_A, m0, chunk);
        load_tile(st + 16384, g_W, n0, chunk);
    };
    auto compute = [&](uint32_t st) {
#pragma unroll
        for (int ks = 0; ks < 4; ++ks) {
            uint32_t ah[2][4], bw[4][4];
            const int rA = lane & 15;
            const int uA = ks * 2 + (lane >> 4);
#pragma unroll
            for (int mi = 0; mi < 2; ++mi)
                ldm_x4(ah[mi], st + swz(m_off + mi * 16 + rA, uA));
            const int rB = (lane & 7) + ((lane >> 4) << 3);
            const int uB = ks * 2 + ((lane >> 3) & 1);
#pragma unroll
            for (int j = 0; j < 4; ++j)
                ldm_x4(bw[j], st + 16384 + swz(n_off + j * 16 + rB, uB));
#pragma unroll
            for (int mi = 0; mi < 2; ++mi)
#pragma unroll
                for (int j = 0; j < 4; ++j) {
                    mma_f16(acc[mi][2 * j],     ah[mi], &bw[j][0]);
                    mma_f16(acc[mi][2 * j + 1], ah[mi], &bw[j][2]);
                }
        }
    };

    load_stage(0, stage_addr(0));
    CP_COMMIT();
    load_stage(1, stage_addr(1));
    CP_COMMIT();

    // single-barrier 3-stage pipeline, prefetch distance 2:
    //   load(c+2) targets slot (c+2)%3 == (c-1)%3 -- every warp has finished
    //   compute(c-1) before passing this iteration's barrier.
    for (int c = 0; c < NCHUNK; ++c) {
        if (c < NCHUNK - 1) { CP_WAIT_1(); } else { CP_WAIT_0(); }
        __syncthreads();                      // stage c resident; compute(c-1) done by all
        if (c + 2 < NCHUNK) {
            load_stage(c + 2, stage_addr(c + 2));
            CP_COMMIT();                      // DMA overlaps compute(c) and compute(c+1)
        }
        compute(stage_addr(c));
    }

    // epilogue: +bias, fp32 out
#pragma unroll
    for (int mi = 0; mi < 2; ++mi) {
        size_t r0 = m0 + m_off + mi * 16 + (lane >> 2);
#pragma unroll
        for (int g = 0; g < 8; ++g) {
            size_t col = n0 + n_off + g * 8 + (lane & 3) * 2;
            float b0v = __ldg(bias + col), b1v = __ldg(bias + col + 1);
            float2 v0 = make_float2(acc[mi][g][0] + b0v, acc[mi][g][1] + b1v);
            float2 v1 = make_float2(acc[mi][g][2] + b0v, acc[mi][g][3] + b1v);
            *reinterpret_cast<float2*>(out + r0 * D_OUT + col) = v0;
            *reinterpret_cast<float2*>(out + (r0 + 8) * D_OUT + col) = v1;
        }
    }
}

// ---------------------------------------------------------------- launch
extern "C" void kernel_launch(void* const* d_in, const int* in_sizes, int n_in,
                              void* d_out, int out_size) {
    const float* x    = (const float*)d_in[0];
    const float* S_in = (const float*)d_in[1];
    // d_in[2] = H_block (Sylvester/sqrt(128), reproduced analytically)
    const float* w    = (const float*)d_in[3];
    const float* la   = (const float*)d_in[4];
    const float* lb   = (const float*)d_in[5];
    const float* bias = (const float*)d_in[6];
    float* out = (float*)d_out;

    cudaFuncSetAttribute(gemm_kernel, cudaFuncAttributeMaxDynamicSharedMemorySize, SMEM_DYN);

    prep_kernel<<<MROWS + D_OUT + RANK, 256>>>(x, S_in, w, lb, la);
    dim3 lgrid(MROWS / 128, KSPLIT);
    lora_r_kernel<<<lgrid, 256>>>();
    lora_fold_kernel<<<(MROWS * RANK) / 256, 256>>>();
    dim3 grid(D_OUT / 128, MROWS / 128);
    gemm_kernel<<<grid, 256, SMEM_DYN>>>(out, bias);
}